// round 10
// baseline (speedup 1.0000x reference)
#include <cuda_runtime.h>
#include <stdint.h>

// NaiveVisCache, two-phase:
//   Kernel A: pack (cache > 128) into a 1.57MB bit table (streaming read of the
//             48MB int32 table, ballot-packed, coalesced). The bit table is
//             small enough to be unconditionally L2-resident.
//   Kernel B: per-ray face select + morton index + single-BIT gather + store.
//
// Semantics (verified rel_err=0.0 in R6/R7/R9): the reference lowers
// v/inf_norm as v * fl_rn(1/inf_norm) -> __frcp_rn + __fmul_rn; the where
// chain falls back to face 0 when x*fl(1/x) rounds below 1.0.

#define MIDPOINT 128

// 128^3 voxels * 6 faces = 12,582,912 entries -> /32 = 393,216 words (1.57MB)
#define N_ENTRIES  12582912
#define N_WORDS    393216
__device__ uint32_t g_bits[N_WORDS];

// ---------------- Kernel A: pack ----------------
// 2048 blocks x 256 threads = 16384 warps; each warp builds 24 words.
// Per iteration: 32 lanes read 32 consecutive int32 (one 128B line, fully
// coalesced), ballot the predicate, lane 0 stores the word.
__global__ void __launch_bounds__(256)
pack_kernel(const int* __restrict__ cache)
{
    int warp_id = (blockIdx.x * blockDim.x + threadIdx.x) >> 5;
    int lane    = threadIdx.x & 31;

    int w0 = warp_id * 24;
    #pragma unroll 4
    for (int it = 0; it < 24; it++) {
        int w = w0 + it;
        int e = (w << 5) + lane;
        int val = __ldcs(&cache[e]);                     // pure stream, evict-first
        unsigned bits = __ballot_sync(0xFFFFFFFFu, val > MIDPOINT);
        if (lane == 0) g_bits[w] = bits;
    }
}

// ---------------- Kernel B: gather ----------------
__device__ __forceinline__ unsigned expand_bits(unsigned v) {
    v = (v | (v << 16)) & 0x030000FFu;
    v = (v | (v << 8))  & 0x0300F00Fu;
    v = (v | (v << 4))  & 0x030C30C3u;
    v = (v | (v << 2))  & 0x09249249u;
    return v;
}

__global__ void __launch_bounds__(256)
vis_cache_kernel(const float4* __restrict__ org4,
                 const float4* __restrict__ dir4,
                 float4*       __restrict__ out4,
                 int n_oct)  // n_rays / 8
{
    int t = blockIdx.x * blockDim.x + threadIdx.x;
    if (t >= n_oct) return;

    // 8 rays = 24 floats = 6 float4 loads per array (evict-first streams).
    float4 o[6], v[6];
    #pragma unroll
    for (int k = 0; k < 6; k++) o[k] = __ldcs(&org4[6 * t + k]);
    #pragma unroll
    for (int k = 0; k < 6; k++) v[k] = __ldcs(&dir4[6 * t + k]);

    const float* of = reinterpret_cast<const float*>(o);
    const float* vf = reinterpret_cast<const float*>(v);

    // Phase 1: morton base indices (exact-integer path).
    unsigned base[8];
    #pragma unroll
    for (int j = 0; j < 8; j++) {
        float cx = fminf(fmaxf((of[3 * j + 0] * 0.5f + 0.5f) * 128.0f, 0.0f), 127.0f);
        float cy = fminf(fmaxf((of[3 * j + 1] * 0.5f + 0.5f) * 128.0f, 0.0f), 127.0f);
        float cz = fminf(fmaxf((of[3 * j + 2] * 0.5f + 0.5f) * 128.0f, 0.0f), 127.0f);

        unsigned idx = expand_bits((unsigned)(int)cx)
                     | (expand_bits((unsigned)(int)cy) << 1)
                     | (expand_bits((unsigned)(int)cz) << 2);
        base[j] = idx * 6u;
    }

    // Phase 2: face select (reciprocal-multiply, bit-matching the reference).
    unsigned entry[8];
    #pragma unroll
    for (int j = 0; j < 8; j++) {
        float a = vf[3 * j + 0];
        float b = vf[3 * j + 1];
        float c = vf[3 * j + 2];

        float n = fmaxf(fabsf(a), fmaxf(fabsf(b), fabsf(c)));
        float r  = __frcp_rn(n);
        float sa = __fmul_rn(a, r);
        float sb = __fmul_rn(b, r);
        float sc = __fmul_rn(c, r);

        int face = 0;
        if (sa >=  1.0f) face = 0;
        if (sa <= -1.0f) face = 1;
        if (sb >=  1.0f) face = 2;
        if (sb <= -1.0f) face = 3;
        if (sc >=  1.0f) face = 4;
        if (sc <= -1.0f) face = 5;

        entry[j] = base[j] + (unsigned)face;
    }

    // Phase 3: 8 independent bit gathers; bit table is L2-resident (1.57MB).
    uint32_t word[8];
    #pragma unroll
    for (int j = 0; j < 8; j++) word[j] = __ldg(&g_bits[entry[j] >> 5]);

    float res[8];
    #pragma unroll
    for (int j = 0; j < 8; j++)
        res[j] = ((word[j] >> (entry[j] & 31u)) & 1u) ? 1.0f : 0.0f;

    __stcs(&out4[2 * t + 0], make_float4(res[0], res[1], res[2], res[3]));
    __stcs(&out4[2 * t + 1], make_float4(res[4], res[5], res[6], res[7]));
}

extern "C" void kernel_launch(void* const* d_in, const int* in_sizes, int n_in,
                              void* d_out, int out_size)
{
    const float4* org4  = (const float4*)d_in[0];
    const float4* dir4  = (const float4*)d_in[1];
    const int*    cache = (const int*)d_in[2];
    float4*       out4  = (float4*)d_out;

    int n_rays = in_sizes[0] / 3;   // 4194304
    int n_oct  = n_rays / 8;        // 524288

    // Kernel A: 2048 blocks x 256 threads = 16384 warps x 24 words = 393216 words.
    pack_kernel<<<2048, 256>>>(cache);

    // Kernel B: gather.
    int threads = 256;
    int blocks  = (n_oct + threads - 1) / threads;
    vis_cache_kernel<<<blocks, threads>>>(org4, dir4, out4, n_oct);
}

// round 11
// speedup vs baseline: 1.5591x; 1.5591x over previous
#include <cuda_runtime.h>
#include <stdint.h>

// NaiveVisCache, two-phase:
//   Kernel A: pack (cache > 128) into a 1.57MB bit table. Loads batched before
//             ballots so MLP=8 per warp (R10's load->ballot interleave choked MLP).
//   Kernel B: per-ray face select + morton index + single-BIT gather + store.
//             4 rays/thread (32-reg shape -> ~90% occupancy, proven in R6).
//
// Semantics (verified rel_err=0.0): reference lowers v/inf_norm as
// v * fl_rn(1/inf_norm) -> __frcp_rn + __fmul_rn; where-chain falls back to
// face 0 when x*fl(1/x) rounds below 1.0.

#define MIDPOINT 128

// 128^3 * 6 = 12,582,912 entries -> 393,216 words (1.57MB)
#define N_WORDS 393216
__device__ uint32_t g_bits[N_WORDS];

// ---------------- Kernel A: pack ----------------
// 6144 blocks x 256 threads = 49152 warps x 8 words each.
__global__ void __launch_bounds__(256)
pack_kernel(const int* __restrict__ cache)
{
    int warp_id = (blockIdx.x * blockDim.x + threadIdx.x) >> 5;
    int lane    = threadIdx.x & 31;

    int w0 = warp_id * 8;
    int base = (w0 << 5) + lane;

    // Batch all 8 coalesced loads first: 8 independent lines in flight.
    int v0 = __ldcs(&cache[base + 0 * 32]);
    int v1 = __ldcs(&cache[base + 1 * 32]);
    int v2 = __ldcs(&cache[base + 2 * 32]);
    int v3 = __ldcs(&cache[base + 3 * 32]);
    int v4 = __ldcs(&cache[base + 4 * 32]);
    int v5 = __ldcs(&cache[base + 5 * 32]);
    int v6 = __ldcs(&cache[base + 6 * 32]);
    int v7 = __ldcs(&cache[base + 7 * 32]);

    unsigned b0 = __ballot_sync(0xFFFFFFFFu, v0 > MIDPOINT);
    unsigned b1 = __ballot_sync(0xFFFFFFFFu, v1 > MIDPOINT);
    unsigned b2 = __ballot_sync(0xFFFFFFFFu, v2 > MIDPOINT);
    unsigned b3 = __ballot_sync(0xFFFFFFFFu, v3 > MIDPOINT);
    unsigned b4 = __ballot_sync(0xFFFFFFFFu, v4 > MIDPOINT);
    unsigned b5 = __ballot_sync(0xFFFFFFFFu, v5 > MIDPOINT);
    unsigned b6 = __ballot_sync(0xFFFFFFFFu, v6 > MIDPOINT);
    unsigned b7 = __ballot_sync(0xFFFFFFFFu, v7 > MIDPOINT);

    if (lane == 0) {
        uint4* dst = reinterpret_cast<uint4*>(&g_bits[w0]);
        dst[0] = make_uint4(b0, b1, b2, b3);
        dst[1] = make_uint4(b4, b5, b6, b7);
    }
}

// ---------------- Kernel B: gather ----------------
__device__ __forceinline__ unsigned expand_bits(unsigned v) {
    v = (v | (v << 16)) & 0x030000FFu;
    v = (v | (v << 8))  & 0x0300F00Fu;
    v = (v | (v << 4))  & 0x030C30C3u;
    v = (v | (v << 2))  & 0x09249249u;
    return v;
}

__global__ void __launch_bounds__(256)
vis_cache_kernel(const float4* __restrict__ org4,
                 const float4* __restrict__ dir4,
                 float4*       __restrict__ out4,
                 int n_quads)  // n_rays / 4
{
    int t = blockIdx.x * blockDim.x + threadIdx.x;
    if (t >= n_quads) return;

    // 4 rays = 12 floats = 3 float4 loads per array (evict-first streams).
    float4 oa = __ldcs(&org4[3 * t + 0]);
    float4 ob = __ldcs(&org4[3 * t + 1]);
    float4 oc = __ldcs(&org4[3 * t + 2]);
    float4 va = __ldcs(&dir4[3 * t + 0]);
    float4 vb = __ldcs(&dir4[3 * t + 1]);
    float4 vc = __ldcs(&dir4[3 * t + 2]);

    float of[12] = {oa.x, oa.y, oa.z, oa.w, ob.x, ob.y, ob.z, ob.w, oc.x, oc.y, oc.z, oc.w};
    float vf[12] = {va.x, va.y, va.z, va.w, vb.x, vb.y, vb.z, vb.w, vc.x, vc.y, vc.z, vc.w};

    // Phase 1: morton base indices (exact-integer path).
    unsigned entry[4];
    #pragma unroll
    for (int j = 0; j < 4; j++) {
        float cx = fminf(fmaxf((of[3 * j + 0] * 0.5f + 0.5f) * 128.0f, 0.0f), 127.0f);
        float cy = fminf(fmaxf((of[3 * j + 1] * 0.5f + 0.5f) * 128.0f, 0.0f), 127.0f);
        float cz = fminf(fmaxf((of[3 * j + 2] * 0.5f + 0.5f) * 128.0f, 0.0f), 127.0f);

        unsigned idx = expand_bits((unsigned)(int)cx)
                     | (expand_bits((unsigned)(int)cy) << 1)
                     | (expand_bits((unsigned)(int)cz) << 2);
        entry[j] = idx * 6u;
    }

    // Phase 2: face select (reciprocal-multiply, bit-matching the reference).
    #pragma unroll
    for (int j = 0; j < 4; j++) {
        float a = vf[3 * j + 0];
        float b = vf[3 * j + 1];
        float c = vf[3 * j + 2];

        float n = fmaxf(fabsf(a), fmaxf(fabsf(b), fabsf(c)));
        float r  = __frcp_rn(n);
        float sa = __fmul_rn(a, r);
        float sb = __fmul_rn(b, r);
        float sc = __fmul_rn(c, r);

        int face = 0;
        if (sa >=  1.0f) face = 0;
        if (sa <= -1.0f) face = 1;
        if (sb >=  1.0f) face = 2;
        if (sb <= -1.0f) face = 3;
        if (sc >=  1.0f) face = 4;
        if (sc <= -1.0f) face = 5;

        entry[j] += (unsigned)face;
    }

    // Phase 3: 4 independent bit gathers; table is L2-resident (1.57MB).
    uint32_t w0 = __ldg(&g_bits[entry[0] >> 5]);
    uint32_t w1 = __ldg(&g_bits[entry[1] >> 5]);
    uint32_t w2 = __ldg(&g_bits[entry[2] >> 5]);
    uint32_t w3 = __ldg(&g_bits[entry[3] >> 5]);

    float4 res = make_float4(
        (w0 >> (entry[0] & 31u)) & 1u ? 1.0f : 0.0f,
        (w1 >> (entry[1] & 31u)) & 1u ? 1.0f : 0.0f,
        (w2 >> (entry[2] & 31u)) & 1u ? 1.0f : 0.0f,
        (w3 >> (entry[3] & 31u)) & 1u ? 1.0f : 0.0f);

    __stcs(&out4[t], res);
}

extern "C" void kernel_launch(void* const* d_in, const int* in_sizes, int n_in,
                              void* d_out, int out_size)
{
    const float4* org4  = (const float4*)d_in[0];
    const float4* dir4  = (const float4*)d_in[1];
    const int*    cache = (const int*)d_in[2];
    float4*       out4  = (float4*)d_out;

    int n_rays  = in_sizes[0] / 3;   // 4194304
    int n_quads = n_rays / 4;        // 1048576

    pack_kernel<<<6144, 256>>>(cache);                       // 49152 warps * 8 words
    vis_cache_kernel<<<(n_quads + 255) / 256, 256>>>(org4, dir4, out4, n_quads);
}

// round 12
// speedup vs baseline: 1.5695x; 1.0067x over previous
#include <cuda_runtime.h>
#include <stdint.h>

// NaiveVisCache, two-phase:
//   Kernel A: pack (cache > 128) -> 1.57MB bit table. 16 loads batched per warp
//             (MLP=16) before any ballot; lane0 stores 4x uint4.
//   Kernel B: face select + morton + bit gather. Each 32-lane divergent gather
//             is SPLIT into 4 predicated LDGs of 8 lanes, converting 32
//             within-LDG replay wavefronts (2.07 cyc/wf) into 4x8 cross-LDG
//             wavefronts (~1.0 cyc/wf) — attacks the measured L1tex floor
//             (28.3k wf/SM * 2.07 ≈ 31us == R11's gather time).
//
// Semantics (verified rel_err=0.0): reference lowers v/inf_norm as
// v * fl_rn(1/inf_norm) -> __frcp_rn + __fmul_rn; where-chain falls back to
// face 0 when x*fl(1/x) rounds below 1.0.

#define MIDPOINT 128

// 128^3 * 6 = 12,582,912 entries -> 393,216 words (1.57MB)
#define N_WORDS 393216
__device__ uint32_t g_bits[N_WORDS];

// ---------------- Kernel A: pack ----------------
// 3072 blocks x 256 threads = 24576 warps x 16 words each.
__global__ void __launch_bounds__(256)
pack_kernel(const int* __restrict__ cache)
{
    int warp_id = (blockIdx.x * blockDim.x + threadIdx.x) >> 5;
    int lane    = threadIdx.x & 31;

    int w0   = warp_id * 16;
    int base = (w0 << 5) + lane;

    int v[16];
    #pragma unroll
    for (int k = 0; k < 16; k++) v[k] = __ldcs(&cache[base + k * 32]);  // MLP=16

    unsigned b[16];
    #pragma unroll
    for (int k = 0; k < 16; k++) b[k] = __ballot_sync(0xFFFFFFFFu, v[k] > MIDPOINT);

    if (lane == 0) {
        uint4* dst = reinterpret_cast<uint4*>(&g_bits[w0]);   // default policy:
        dst[0] = make_uint4(b[0],  b[1],  b[2],  b[3]);       // bits stay in L2
        dst[1] = make_uint4(b[4],  b[5],  b[6],  b[7]);
        dst[2] = make_uint4(b[8],  b[9],  b[10], b[11]);
        dst[3] = make_uint4(b[12], b[13], b[14], b[15]);
    }
}

// ---------------- Kernel B: gather ----------------
__device__ __forceinline__ unsigned expand_bits(unsigned v) {
    v = (v | (v << 16)) & 0x030000FFu;
    v = (v | (v << 8))  & 0x0300F00Fu;
    v = (v | (v << 4))  & 0x030C30C3u;
    v = (v | (v << 2))  & 0x09249249u;
    return v;
}

// One logical warp-gather issued as 4 predicated LDGs (8 active lanes each).
// Every lane is active in exactly one instruction, loading its own address.
__device__ __forceinline__ uint32_t gather_split(const uint32_t* p, unsigned grp) {
    uint32_t w;
    asm volatile("{\n\t"
        ".reg .pred q0, q1, q2, q3;\n\t"
        "setp.eq.u32 q0, %2, 0;\n\t"
        "setp.eq.u32 q1, %2, 1;\n\t"
        "setp.eq.u32 q2, %2, 2;\n\t"
        "setp.eq.u32 q3, %2, 3;\n\t"
        "@q0 ld.global.nc.u32 %0, [%1];\n\t"
        "@q1 ld.global.nc.u32 %0, [%1];\n\t"
        "@q2 ld.global.nc.u32 %0, [%1];\n\t"
        "@q3 ld.global.nc.u32 %0, [%1];\n\t"
        "}" : "=r"(w) : "l"(p), "r"(grp));
    return w;
}

__global__ void __launch_bounds__(256)
vis_cache_kernel(const float4* __restrict__ org4,
                 const float4* __restrict__ dir4,
                 float4*       __restrict__ out4,
                 int n_quads)  // n_rays / 4
{
    int t = blockIdx.x * blockDim.x + threadIdx.x;
    if (t >= n_quads) return;

    unsigned grp = (threadIdx.x >> 3) & 3u;   // 8-lane quarter-warp id

    // 4 rays = 12 floats = 3 float4 loads per array (evict-first streams).
    float4 oa = __ldcs(&org4[3 * t + 0]);
    float4 ob = __ldcs(&org4[3 * t + 1]);
    float4 oc = __ldcs(&org4[3 * t + 2]);
    float4 va = __ldcs(&dir4[3 * t + 0]);
    float4 vb = __ldcs(&dir4[3 * t + 1]);
    float4 vc = __ldcs(&dir4[3 * t + 2]);

    float of[12] = {oa.x, oa.y, oa.z, oa.w, ob.x, ob.y, ob.z, ob.w, oc.x, oc.y, oc.z, oc.w};
    float vf[12] = {va.x, va.y, va.z, va.w, vb.x, vb.y, vb.z, vb.w, vc.x, vc.y, vc.z, vc.w};

    // Phase 1: morton base indices (exact-integer path).
    unsigned entry[4];
    #pragma unroll
    for (int j = 0; j < 4; j++) {
        float cx = fminf(fmaxf((of[3 * j + 0] * 0.5f + 0.5f) * 128.0f, 0.0f), 127.0f);
        float cy = fminf(fmaxf((of[3 * j + 1] * 0.5f + 0.5f) * 128.0f, 0.0f), 127.0f);
        float cz = fminf(fmaxf((of[3 * j + 2] * 0.5f + 0.5f) * 128.0f, 0.0f), 127.0f);

        unsigned idx = expand_bits((unsigned)(int)cx)
                     | (expand_bits((unsigned)(int)cy) << 1)
                     | (expand_bits((unsigned)(int)cz) << 2);
        entry[j] = idx * 6u;
    }

    // Phase 2: face select (reciprocal-multiply, bit-matching the reference).
    #pragma unroll
    for (int j = 0; j < 4; j++) {
        float a = vf[3 * j + 0];
        float b = vf[3 * j + 1];
        float c = vf[3 * j + 2];

        float n = fmaxf(fabsf(a), fmaxf(fabsf(b), fabsf(c)));
        float r  = __frcp_rn(n);
        float sa = __fmul_rn(a, r);
        float sb = __fmul_rn(b, r);
        float sc = __fmul_rn(c, r);

        int face = 0;
        if (sa >=  1.0f) face = 0;
        if (sa <= -1.0f) face = 1;
        if (sb >=  1.0f) face = 2;
        if (sb <= -1.0f) face = 3;
        if (sc >=  1.0f) face = 4;
        if (sc <= -1.0f) face = 5;

        entry[j] += (unsigned)face;
    }

    // Phase 3: 4 independent bit gathers, each split 4-way across lane groups.
    uint32_t w0 = gather_split(&g_bits[entry[0] >> 5], grp);
    uint32_t w1 = gather_split(&g_bits[entry[1] >> 5], grp);
    uint32_t w2 = gather_split(&g_bits[entry[2] >> 5], grp);
    uint32_t w3 = gather_split(&g_bits[entry[3] >> 5], grp);

    float4 res = make_float4(
        (w0 >> (entry[0] & 31u)) & 1u ? 1.0f : 0.0f,
        (w1 >> (entry[1] & 31u)) & 1u ? 1.0f : 0.0f,
        (w2 >> (entry[2] & 31u)) & 1u ? 1.0f : 0.0f,
        (w3 >> (entry[3] & 31u)) & 1u ? 1.0f : 0.0f);

    __stcs(&out4[t], res);
}

extern "C" void kernel_launch(void* const* d_in, const int* in_sizes, int n_in,
                              void* d_out, int out_size)
{
    const float4* org4  = (const float4*)d_in[0];
    const float4* dir4  = (const float4*)d_in[1];
    const int*    cache = (const int*)d_in[2];
    float4*       out4  = (float4*)d_out;

    int n_rays  = in_sizes[0] / 3;   // 4194304
    int n_quads = n_rays / 4;        // 1048576

    pack_kernel<<<3072, 256>>>(cache);                       // 24576 warps * 16 words
    vis_cache_kernel<<<(n_quads + 255) / 256, 256>>>(org4, dir4, out4, n_quads);
}

// round 13
// speedup vs baseline: 1.8183x; 1.1585x over previous
#include <cuda_runtime.h>
#include <stdint.h>

// NaiveVisCache, single kernel: face select + morton3d + int-table gather.
// d_in[0] = norm_ray_origins (B,3) f32, d_in[1] = viewdirs (B,3) f32,
// d_in[2] = cache (128^3,6) int32. Output: B f32 (0.0/1.0).
//
// Semantics (verified rel_err=0.0 across R6-R12): reference lowers v/inf_norm
// as v * fl_rn(1/inf_norm) -> __frcp_rn + __fmul_rn; where-chain falls back to
// face 0 when x*fl(1/x) rounds below 1.0 (~13.9% of rays).
//
// Shape: completes the {rays/thread} x {cache hints} experiment matrix --
// 4 rays/thread (32 regs, ~90% occ, R6/R12-proven) + __ldcs/__stcs streams
// (R7-proven -36MB DRAM). High occupancy feeds outstanding DRAM misses (BW);
// hints keep the 48MB table hot in L2 (traffic).

#define MIDPOINT 128

__device__ __forceinline__ unsigned expand_bits(unsigned v) {
    v = (v | (v << 16)) & 0x030000FFu;
    v = (v | (v << 8))  & 0x0300F00Fu;
    v = (v | (v << 4))  & 0x030C30C3u;
    v = (v | (v << 2))  & 0x09249249u;
    return v;
}

__global__ void __launch_bounds__(256)
vis_cache_kernel(const float4* __restrict__ org4,
                 const float4* __restrict__ dir4,
                 const int*    __restrict__ cache,
                 float4*       __restrict__ out4,
                 int n_quads)  // n_rays / 4
{
    int t = blockIdx.x * blockDim.x + threadIdx.x;
    if (t >= n_quads) return;

    // 4 rays = 12 floats = 3 float4 loads per array (evict-first streams).
    float4 oa = __ldcs(&org4[3 * t + 0]);
    float4 ob = __ldcs(&org4[3 * t + 1]);
    float4 oc = __ldcs(&org4[3 * t + 2]);
    float4 va = __ldcs(&dir4[3 * t + 0]);
    float4 vb = __ldcs(&dir4[3 * t + 1]);
    float4 vc = __ldcs(&dir4[3 * t + 2]);

    float of[12] = {oa.x, oa.y, oa.z, oa.w, ob.x, ob.y, ob.z, ob.w, oc.x, oc.y, oc.z, oc.w};
    float vf[12] = {va.x, va.y, va.z, va.w, vb.x, vb.y, vb.z, vb.w, vc.x, vc.y, vc.z, vc.w};

    // Phase 1: morton base indices (exact-integer path).
    unsigned entry[4];
    #pragma unroll
    for (int j = 0; j < 4; j++) {
        float cx = fminf(fmaxf((of[3 * j + 0] * 0.5f + 0.5f) * 128.0f, 0.0f), 127.0f);
        float cy = fminf(fmaxf((of[3 * j + 1] * 0.5f + 0.5f) * 128.0f, 0.0f), 127.0f);
        float cz = fminf(fmaxf((of[3 * j + 2] * 0.5f + 0.5f) * 128.0f, 0.0f), 127.0f);

        unsigned idx = expand_bits((unsigned)(int)cx)
                     | (expand_bits((unsigned)(int)cy) << 1)
                     | (expand_bits((unsigned)(int)cz) << 2);
        entry[j] = idx * 6u;
    }

    // Phase 2: face select (reciprocal-multiply, bit-matching the reference).
    #pragma unroll
    for (int j = 0; j < 4; j++) {
        float a = vf[3 * j + 0];
        float b = vf[3 * j + 1];
        float c = vf[3 * j + 2];

        float n = fmaxf(fabsf(a), fmaxf(fabsf(b), fabsf(c)));
        float r  = __frcp_rn(n);
        float sa = __fmul_rn(a, r);
        float sb = __fmul_rn(b, r);
        float sc = __fmul_rn(c, r);

        int face = 0;
        if (sa >=  1.0f) face = 0;
        if (sa <= -1.0f) face = 1;
        if (sb >=  1.0f) face = 2;
        if (sb <= -1.0f) face = 3;
        if (sc >=  1.0f) face = 4;
        if (sc <= -1.0f) face = 5;

        entry[j] += (unsigned)face;
    }

    // Phase 3: 4 independent gathers in flight (default policy: table owns L2).
    int v0 = __ldg(&cache[entry[0]]);
    int v1 = __ldg(&cache[entry[1]]);
    int v2 = __ldg(&cache[entry[2]]);
    int v3 = __ldg(&cache[entry[3]]);

    float4 res = make_float4(v0 > MIDPOINT ? 1.0f : 0.0f,
                             v1 > MIDPOINT ? 1.0f : 0.0f,
                             v2 > MIDPOINT ? 1.0f : 0.0f,
                             v3 > MIDPOINT ? 1.0f : 0.0f);

    __stcs(&out4[t], res);   // never re-read: stream out
}

extern "C" void kernel_launch(void* const* d_in, const int* in_sizes, int n_in,
                              void* d_out, int out_size)
{
    const float4* org4  = (const float4*)d_in[0];
    const float4* dir4  = (const float4*)d_in[1];
    const int*    cache = (const int*)d_in[2];
    float4*       out4  = (float4*)d_out;

    int n_rays  = in_sizes[0] / 3;   // 4194304
    int n_quads = n_rays / 4;        // 1048576

    vis_cache_kernel<<<(n_quads + 255) / 256, 256>>>(org4, dir4, cache, out4, n_quads);
}